// round 9
// baseline (speedup 1.0000x reference)
#include <cuda_runtime.h>
#include <math.h>

// Problem constants
#define BB 64
#define TT 512
#define CC 384
#define HH 64

// Scratch for Q, K, V projections (8 MB each) — device globals, no allocation.
__device__ float g_q[BB * TT * HH];
__device__ float g_k[BB * TT * HH];
__device__ float g_v[BB * TT * HH];

// ---------------------------------------------------------------------------
// Projection kernel: out[m, h] = sum_c x[m, c] * W[c, h]
// M = B*T = 32768, K = 384, N = 64. Grid: (M/128, 3 weight matrices).
// Block 256 threads, 128x64 output tile, 8x4 register micro-tile per thread.
// A tile stored TRANSPOSED (k-major) in smem -> inner loop: 3 LDS.128, 32 FFMA.
// ---------------------------------------------------------------------------
#define AT_STRIDE 132   // 128 + 4: keeps float4 aligned, write conflicts only 4-way

__global__ __launch_bounds__(256) void proj_kernel(
    const float* __restrict__ x,
    const float* __restrict__ Wq,
    const float* __restrict__ Wk,
    const float* __restrict__ Wv)
{
    __shared__ __align__(16) float At[32][AT_STRIDE];  // x tile, transposed [k][m]
    __shared__ __align__(16) float Bs[32][68];         // W tile [k][n], padded

    const int mt    = blockIdx.x;     // 0..255
    const int which = blockIdx.y;     // 0:Q 1:K 2:V
    const float* W  = (which == 0) ? Wq : (which == 1) ? Wk : Wv;
    float* outp     = (which == 0) ? g_q : (which == 1) ? g_k : g_v;

    const int tid = threadIdx.x;
    const int tx  = tid & 15;         // output cols tx*4 .. +3
    const int ty  = tid >> 4;         // output rows ty*8 .. +7
    const int m0  = mt * 128;

    float acc[8][4];
#pragma unroll
    for (int i = 0; i < 8; i++)
#pragma unroll
        for (int j = 0; j < 4; j++) acc[i][j] = 0.f;

    for (int k0 = 0; k0 < CC; k0 += 32) {
        // Load A tile 128x32, store transposed At[k][m]. Coalesced float4 reads.
        {
            const int c4 = (tid & 7) * 4;    // k within chunk
            const int r0 = tid >> 3;         // m within tile
#pragma unroll
            for (int rr = r0; rr < 128; rr += 32) {
                const float4 v = *(const float4*)&x[(size_t)(m0 + rr) * CC + k0 + c4];
                At[c4 + 0][rr] = v.x;
                At[c4 + 1][rr] = v.y;
                At[c4 + 2][rr] = v.z;
                At[c4 + 3][rr] = v.w;
            }
        }
        // Load B tile 32x64 (coalesced, conflict-free)
        {
            const int c  = tid & 63;
            const int r0 = tid >> 6;
#pragma unroll
            for (int r = r0; r < 32; r += 4)
                Bs[r][c] = W[(k0 + r) * HH + c];
        }
        __syncthreads();

#pragma unroll 8
        for (int k = 0; k < 32; k++) {
            const float4 a0 = *(const float4*)&At[k][ty * 8];
            const float4 a1 = *(const float4*)&At[k][ty * 8 + 4];
            const float4 b  = *(const float4*)&Bs[k][tx * 4];
            float av[8] = {a0.x, a0.y, a0.z, a0.w, a1.x, a1.y, a1.z, a1.w};
#pragma unroll
            for (int i = 0; i < 8; i++) {
                acc[i][0] += av[i] * b.x;
                acc[i][1] += av[i] * b.y;
                acc[i][2] += av[i] * b.z;
                acc[i][3] += av[i] * b.w;
            }
        }
        __syncthreads();
    }

#pragma unroll
    for (int i = 0; i < 8; i++) {
        float4 r;
        r.x = acc[i][0]; r.y = acc[i][1]; r.z = acc[i][2]; r.w = acc[i][3];
        *(float4*)&outp[(size_t)(m0 + ty * 8 + i) * HH + tx * 4] = r;
    }
}

// ---------------------------------------------------------------------------
// Fused causal attention with online softmax (flash-attention style).
// Grid: (T/64 q-tiles, B). Block 128 threads (16 tx x 8 ty).
// Thread owns 8x4 tile: q rows ty*8+i, key/head cols tx*4+j.
// Q is pre-scaled by 1/sqrt(H) at load. P rows live within one warp, so the
// P-visibility barrier is __syncwarp() only.
// ---------------------------------------------------------------------------
#define QT_STRIDE 68   // pad: keeps float4 16B-aligned, kills bank conflicts

__global__ __launch_bounds__(128) void attn_kernel(float* __restrict__ out)
{
    extern __shared__ __align__(16) float sm[];
    float (*Qt)[QT_STRIDE] = (float(*)[QT_STRIDE])sm;                       // [H][64] Q^T (pre-scaled)
    float (*Kt)[QT_STRIDE] = (float(*)[QT_STRIDE])(sm + 64 * QT_STRIDE);    // [H][64] K^T
    float (*Vs)[64]        = (float(*)[64])(sm + 2 * 64 * QT_STRIDE);       // [64][H] V natural
    float (*Ps)[QT_STRIDE] = (float(*)[QT_STRIDE])(sm + 2 * 64 * QT_STRIDE + 64 * 64); // [64][64] P

    const int qt  = (int)gridDim.x - 1 - (int)blockIdx.x;  // heavy tiles first
    const int b   = blockIdx.y;
    const int tid = threadIdx.x;
    const int tx  = tid & 15;
    const int ty  = tid >> 4;   // 0..7

    const float scale = 0.125f;   // 1/sqrt(64), folded into Q

    // Load Q tile transposed + pre-scaled: Qt[h][r] = Q[r][h] * scale
    {
        const float* qb = g_q + ((size_t)b * TT + qt * 64) * HH;
        const int c4 = (tid & 15) * 4;   // h
        const int r0 = tid >> 4;         // q row
#pragma unroll
        for (int rr = r0; rr < 64; rr += 8) {
            const float4 v = *(const float4*)&qb[rr * HH + c4];
            Qt[c4 + 0][rr] = v.x * scale;
            Qt[c4 + 1][rr] = v.y * scale;
            Qt[c4 + 2][rr] = v.z * scale;
            Qt[c4 + 3][rr] = v.w * scale;
        }
    }

    float m_i[8], l_i[8], o[8][4];
#pragma unroll
    for (int i = 0; i < 8; i++) {
        m_i[i] = -1e30f;
        l_i[i] = 0.f;
#pragma unroll
        for (int j = 0; j < 4; j++) o[i][j] = 0.f;
    }

    for (int kt = 0; kt <= qt; kt++) {
        __syncthreads();  // prior tile's reads of Kt/Vs done (and Q load on iter 0)

        // Load K tile transposed
        {
            const float* kb = g_k + ((size_t)b * TT + kt * 64) * HH;
            const int c4 = (tid & 15) * 4;
            const int r0 = tid >> 4;
#pragma unroll
            for (int rr = r0; rr < 64; rr += 8) {
                const float4 v = *(const float4*)&kb[rr * HH + c4];
                Kt[c4 + 0][rr] = v.x;
                Kt[c4 + 1][rr] = v.y;
                Kt[c4 + 2][rr] = v.z;
                Kt[c4 + 3][rr] = v.w;
            }
        }
        // Load V tile natural (straight float4 copy)
        {
            const float4* v4  = (const float4*)(g_v + ((size_t)b * TT + kt * 64) * HH);
            float4*       vs4 = (float4*)Vs;
#pragma unroll
            for (int i = tid; i < 64 * (HH / 4); i += 128) vs4[i] = v4[i];
        }
        __syncthreads();

        // S = Q K^T (8x4 per thread); scale already folded into Q
        float s[8][4];
#pragma unroll
        for (int i = 0; i < 8; i++)
#pragma unroll
            for (int j = 0; j < 4; j++) s[i][j] = 0.f;

#pragma unroll 8
        for (int h = 0; h < HH; h++) {
            const float4 q0 = *(const float4*)&Qt[h][ty * 8];
            const float4 q1 = *(const float4*)&Qt[h][ty * 8 + 4];
            const float4 k4 = *(const float4*)&Kt[h][tx * 4];
            float qv[8] = {q0.x, q0.y, q0.z, q0.w, q1.x, q1.y, q1.z, q1.w};
#pragma unroll
            for (int i = 0; i < 8; i++) {
                s[i][0] += qv[i] * k4.x;
                s[i][1] += qv[i] * k4.y;
                s[i][2] += qv[i] * k4.z;
                s[i][3] += qv[i] * k4.w;
            }
        }

        // causal mask (only the diagonal tile has masked entries)
        if (kt == qt) {
#pragma unroll
            for (int i = 0; i < 8; i++)
#pragma unroll
                for (int j = 0; j < 4; j++)
                    if (tx * 4 + j > ty * 8 + i) s[i][j] = -1e30f;
        }

        // online softmax update per q row (row spread over 16 tx lanes of one warp)
#pragma unroll
        for (int i = 0; i < 8; i++) {
            float v = fmaxf(fmaxf(s[i][0], s[i][1]), fmaxf(s[i][2], s[i][3]));
#pragma unroll
            for (int off = 8; off >= 1; off >>= 1)
                v = fmaxf(v, __shfl_xor_sync(0xffffffffu, v, off));
            const float mnew  = fmaxf(m_i[i], v);
            const float alpha = __expf(m_i[i] - mnew);
            m_i[i] = mnew;

            float4 p;
            p.x = __expf(s[i][0] - mnew);
            p.y = __expf(s[i][1] - mnew);
            p.z = __expf(s[i][2] - mnew);
            p.w = __expf(s[i][3] - mnew);
            float rs = p.x + p.y + p.z + p.w;
#pragma unroll
            for (int off = 8; off >= 1; off >>= 1)
                rs += __shfl_xor_sync(0xffffffffu, rs, off);
            l_i[i] = l_i[i] * alpha + rs;

            *(float4*)&Ps[ty * 8 + i][tx * 4] = p;

            o[i][0] *= alpha; o[i][1] *= alpha; o[i][2] *= alpha; o[i][3] *= alpha;
        }
        // P rows [16w .. 16w+15] are written and read only by warp w:
        __syncwarp();

        // O += P @ V
#pragma unroll 8
        for (int kv = 0; kv < 64; kv++) {
            float av[8];
#pragma unroll
            for (int i = 0; i < 8; i++) av[i] = Ps[ty * 8 + i][kv];
            const float4 v4 = *(const float4*)&Vs[kv][tx * 4];
#pragma unroll
            for (int i = 0; i < 8; i++) {
                o[i][0] += av[i] * v4.x;
                o[i][1] += av[i] * v4.y;
                o[i][2] += av[i] * v4.z;
                o[i][3] += av[i] * v4.w;
            }
        }
    }

    // epilogue: normalize and store
#pragma unroll
    for (int i = 0; i < 8; i++) {
        const float inv = 1.f / l_i[i];
        float4 r;
        r.x = o[i][0] * inv; r.y = o[i][1] * inv; r.z = o[i][2] * inv; r.w = o[i][3] * inv;
        *(float4*)&out[((size_t)b * TT + qt * 64 + ty * 8 + i) * HH + tx * 4] = r;
    }
}

// ---------------------------------------------------------------------------
// Launch
// ---------------------------------------------------------------------------
extern "C" void kernel_launch(void* const* d_in, const int* in_sizes, int n_in,
                              void* d_out, int out_size)
{
    const float* x  = (const float*)d_in[0];
    const float* Wq = (const float*)d_in[1];
    const float* Wk = (const float*)d_in[2];
    const float* Wv = (const float*)d_in[3];
    float* out = (float*)d_out;

    (void)in_sizes; (void)n_in; (void)out_size;

    // QKV projection
    {
        dim3 grid(BB * TT / 128, 3);
        proj_kernel<<<grid, 256>>>(x, Wq, Wk, Wv);
    }

    // Fused attention
    {
        const int smem_bytes = (3 * 64 * QT_STRIDE + 64 * 64) * (int)sizeof(float);
        cudaFuncSetAttribute(attn_kernel, cudaFuncAttributeMaxDynamicSharedMemorySize, smem_bytes);
        dim3 grid(TT / 64, BB);
        attn_kernel<<<grid, 128, smem_bytes>>>(out);
    }
}

// round 13
// speedup vs baseline: 1.6041x; 1.6041x over previous
#include <cuda_runtime.h>
#include <math.h>
#include <stdint.h>

// Problem constants
#define BB 64
#define TT 512
#define CC 384
#define HH 64

// Scratch for Q, K, V projections (8 MB each) — device globals, no allocation.
__device__ float g_q[BB * TT * HH];
__device__ float g_k[BB * TT * HH];
__device__ float g_v[BB * TT * HH];

// ---------------------------------------------------------------------------
// tf32 helpers
// ---------------------------------------------------------------------------
__device__ __forceinline__ uint32_t f2tf32(float f) {
    uint32_t u;
    asm("cvt.rna.tf32.f32 %0, %1;" : "=r"(u) : "f"(f));
    return u;
}

__device__ __forceinline__ void mma_tf32(float c[4], const uint32_t a[4],
                                         uint32_t b0, uint32_t b1) {
    asm volatile(
        "mma.sync.aligned.m16n8k8.row.col.f32.tf32.tf32.f32 "
        "{%0,%1,%2,%3}, {%4,%5,%6,%7}, {%8,%9}, {%0,%1,%2,%3};\n"
        : "+f"(c[0]), "+f"(c[1]), "+f"(c[2]), "+f"(c[3])
        : "r"(a[0]), "r"(a[1]), "r"(a[2]), "r"(a[3]), "r"(b0), "r"(b1));
}

// ---------------------------------------------------------------------------
// Projection kernel (tensor cores, tf32): out[m, h] = sum_c x[m, c] * W[c, h]
// M = 32768, K = 384, N = 64. Grid: (M/256, 3). Block 256 threads = 8 warps.
// Each warp computes a 32x64 strip: 2 m-tiles x 8 n-tiles of m16n8k8.
// Smem strides chosen so A/B fragment loads are bank-conflict-free.
// ---------------------------------------------------------------------------
#define XS_ST 36   // A-frag bank = (g*36 + t) % 32 = g*4 + t -> 32 distinct
#define WS_ST 72   // holds 64-wide tile; B-frag bank = (t*72 + j*8 + g) % 32 = (t*8 + g + j*8) % 32 -> 32 distinct

__global__ __launch_bounds__(256) void proj_kernel(
    const float* __restrict__ x,
    const float* __restrict__ Wq,
    const float* __restrict__ Wk,
    const float* __restrict__ Wv)
{
    __shared__ __align__(16) uint32_t xs[256][XS_ST];  // x tile (tf32 bits), [m][k]
    __shared__ __align__(16) uint32_t ws[32][WS_ST];   // W tile (tf32 bits), [k][n]

    const int mt    = blockIdx.x;     // 0..127
    const int which = blockIdx.y;     // 0:Q 1:K 2:V
    const float* W  = (which == 0) ? Wq : (which == 1) ? Wk : Wv;
    float* outp     = (which == 0) ? g_q : (which == 1) ? g_k : g_v;

    const int tid  = threadIdx.x;
    const int warp = tid >> 5;
    const int lane = tid & 31;
    const int g    = lane >> 2;       // groupID (row within frag)
    const int t    = lane & 3;        // threadID-in-group (col within frag)
    const int m0   = mt * 256;
    const int mw   = warp * 32;       // warp's row strip within the tile

    float cf[16][4];                  // [mi*8 + j][4] accumulators
#pragma unroll
    for (int i = 0; i < 16; i++)
#pragma unroll
        for (int j = 0; j < 4; j++) cf[i][j] = 0.f;

    // thread-static load coords
    const int xc4 = (tid & 7) * 4;    // k col (float4) for x tile
    const int xr0 = tid >> 3;         // row base for x tile
    const int wc4 = (tid & 15) * 4;   // n col (float4) for W tile
    const int wr0 = tid >> 4;         // k row base for W tile

    for (int k0 = 0; k0 < CC; k0 += 32) {
        // Load x tile 256x32 (coalesced float4), cvt to tf32, store row-major
#pragma unroll
        for (int rr = xr0; rr < 256; rr += 32) {
            const float4 v = *(const float4*)&x[(size_t)(m0 + rr) * CC + k0 + xc4];
            uint4 u;
            u.x = f2tf32(v.x); u.y = f2tf32(v.y);
            u.z = f2tf32(v.z); u.w = f2tf32(v.w);
            *(uint4*)&xs[rr][xc4] = u;
        }
        // Load W tile 32x64, cvt to tf32
#pragma unroll
        for (int rr = wr0; rr < 32; rr += 16) {
            const float4 v = *(const float4*)&W[(k0 + rr) * HH + wc4];
            uint4 u;
            u.x = f2tf32(v.x); u.y = f2tf32(v.y);
            u.z = f2tf32(v.z); u.w = f2tf32(v.w);
            *(uint4*)&ws[rr][wc4] = u;
        }
        __syncthreads();

#pragma unroll
        for (int ks = 0; ks < 32; ks += 8) {
            uint32_t a0[4], a1[4];
            a0[0] = xs[mw + g     ][ks + t    ];
            a0[1] = xs[mw + g +  8][ks + t    ];
            a0[2] = xs[mw + g     ][ks + t + 4];
            a0[3] = xs[mw + g +  8][ks + t + 4];
            a1[0] = xs[mw + g + 16][ks + t    ];
            a1[1] = xs[mw + g + 24][ks + t    ];
            a1[2] = xs[mw + g + 16][ks + t + 4];
            a1[3] = xs[mw + g + 24][ks + t + 4];
#pragma unroll
            for (int j = 0; j < 8; j++) {
                const uint32_t b0 = ws[ks + t    ][j * 8 + g];
                const uint32_t b1 = ws[ks + t + 4][j * 8 + g];
                mma_tf32(cf[j],     a0, b0, b1);
                mma_tf32(cf[8 + j], a1, b0, b1);
            }
        }
        __syncthreads();
    }

    // Store: c0,c1 -> (row, 2t), (row, 2t+1); c2,c3 -> row+8
#pragma unroll
    for (int mi = 0; mi < 2; mi++) {
#pragma unroll
        for (int j = 0; j < 8; j++) {
            const int row = m0 + mw + mi * 16 + g;
            const int col = j * 8 + 2 * t;
            float2 lo, hi;
            lo.x = cf[mi * 8 + j][0]; lo.y = cf[mi * 8 + j][1];
            hi.x = cf[mi * 8 + j][2]; hi.y = cf[mi * 8 + j][3];
            *(float2*)&outp[(size_t)row * HH + col]       = lo;
            *(float2*)&outp[(size_t)(row + 8) * HH + col] = hi;
        }
    }
}

// ---------------------------------------------------------------------------
// Fused causal attention with online softmax (flash-attention style).
// Grid: (T/64 q-tiles, B). Block 256 threads. (Proven R6 configuration.)
// Thread (ty, tx) owns a 4x4 tile: q rows ty*4+i, cols tx*4+j.
// Q pre-scaled by 1/sqrt(H); P rows are warp-local -> __syncwarp only.
// ---------------------------------------------------------------------------
#define QT_STRIDE 68   // pad: keeps float4 16B-aligned, kills bank conflicts

__global__ __launch_bounds__(256) void attn_kernel(float* __restrict__ out)
{
    extern __shared__ __align__(16) float sm[];
    float (*Qt)[QT_STRIDE] = (float(*)[QT_STRIDE])sm;                       // [H][64] Q^T (pre-scaled)
    float (*Kt)[QT_STRIDE] = (float(*)[QT_STRIDE])(sm + 64 * QT_STRIDE);    // [H][64] K^T
    float (*Vs)[64]        = (float(*)[64])(sm + 2 * 64 * QT_STRIDE);       // [64][H] V natural
    float (*Ps)[QT_STRIDE] = (float(*)[QT_STRIDE])(sm + 2 * 64 * QT_STRIDE + 64 * 64); // [64][64] P

    const int qt  = (int)gridDim.x - 1 - (int)blockIdx.x;  // heavy tiles first
    const int b   = blockIdx.y;
    const int tid = threadIdx.x;
    const int tx  = tid & 15;
    const int ty  = tid >> 4;

    const float scale = 0.125f;   // 1/sqrt(64), folded into Q at load

    // Load Q tile transposed + pre-scaled: Qt[h][r] = Q[r][h] * scale
    {
        const float* qb = g_q + ((size_t)b * TT + qt * 64) * HH;
        const int c  = tid & 63;   // h
        const int r0 = tid >> 6;
#pragma unroll
        for (int r = r0; r < 64; r += 4)
            Qt[c][r] = qb[r * HH + c] * scale;
    }

    float m_i[4], l_i[4], o[4][4];
#pragma unroll
    for (int i = 0; i < 4; i++) {
        m_i[i] = -1e30f;
        l_i[i] = 0.f;
#pragma unroll
        for (int j = 0; j < 4; j++) o[i][j] = 0.f;
    }

    for (int kt = 0; kt <= qt; kt++) {
        __syncthreads();  // prior PV done (and Q load done on iter 0) before overwriting tiles

        // Load K tile transposed, V tile natural
        {
            const float* kb = g_k + ((size_t)b * TT + kt * 64) * HH;
            const int c  = tid & 63;
            const int r0 = tid >> 6;
#pragma unroll
            for (int r = r0; r < 64; r += 4)
                Kt[c][r] = kb[r * HH + c];
        }
        {
            const float4* v4  = (const float4*)(g_v + ((size_t)b * TT + kt * 64) * HH);
            float4*       vs4 = (float4*)Vs;
#pragma unroll
            for (int i = tid; i < 64 * (HH / 4); i += 256) vs4[i] = v4[i];
        }
        __syncthreads();

        // S = Q K^T  (4x4 per thread); scale already folded into Q
        float s[4][4];
#pragma unroll
        for (int i = 0; i < 4; i++)
#pragma unroll
            for (int j = 0; j < 4; j++) s[i][j] = 0.f;

#pragma unroll 8
        for (int h = 0; h < HH; h++) {
            const float4 a  = *(const float4*)&Qt[h][ty * 4];
            const float4 k4 = *(const float4*)&Kt[h][tx * 4];
            s[0][0] += a.x * k4.x; s[0][1] += a.x * k4.y; s[0][2] += a.x * k4.z; s[0][3] += a.x * k4.w;
            s[1][0] += a.y * k4.x; s[1][1] += a.y * k4.y; s[1][2] += a.y * k4.z; s[1][3] += a.y * k4.w;
            s[2][0] += a.z * k4.x; s[2][1] += a.z * k4.y; s[2][2] += a.z * k4.z; s[2][3] += a.z * k4.w;
            s[3][0] += a.w * k4.x; s[3][1] += a.w * k4.y; s[3][2] += a.w * k4.z; s[3][3] += a.w * k4.w;
        }

        // causal mask (only the diagonal tile has masked entries)
        if (kt == qt) {
#pragma unroll
            for (int i = 0; i < 4; i++)
#pragma unroll
                for (int j = 0; j < 4; j++)
                    if (tx * 4 + j > ty * 4 + i) s[i][j] = -1e30f;
        }

        // online softmax update per q row (row spread over 16 tx lanes of one warp)
#pragma unroll
        for (int i = 0; i < 4; i++) {
            float v = fmaxf(fmaxf(s[i][0], s[i][1]), fmaxf(s[i][2], s[i][3]));
#pragma unroll
            for (int off = 8; off >= 1; off >>= 1)
                v = fmaxf(v, __shfl_xor_sync(0xffffffffu, v, off));
            const float mnew  = fmaxf(m_i[i], v);
            const float alpha = __expf(m_i[i] - mnew);
            m_i[i] = mnew;

            float4 p;
            p.x = __expf(s[i][0] - mnew);
            p.y = __expf(s[i][1] - mnew);
            p.z = __expf(s[i][2] - mnew);
            p.w = __expf(s[i][3] - mnew);
            float rs = p.x + p.y + p.z + p.w;
#pragma unroll
            for (int off = 8; off >= 1; off >>= 1)
                rs += __shfl_xor_sync(0xffffffffu, rs, off);
            l_i[i] = l_i[i] * alpha + rs;

            *(float4*)&Ps[ty * 4 + i][tx * 4] = p;

            o[i][0] *= alpha; o[i][1] *= alpha; o[i][2] *= alpha; o[i][3] *= alpha;
        }
        // P rows ty*4..ty*4+3 are produced and consumed within this warp:
        __syncwarp();

        // O += P @ V
#pragma unroll 8
        for (int kv = 0; kv < 64; kv++) {
            const float a0 = Ps[ty * 4 + 0][kv];
            const float a1 = Ps[ty * 4 + 1][kv];
            const float a2 = Ps[ty * 4 + 2][kv];
            const float a3 = Ps[ty * 4 + 3][kv];
            const float4 v4 = *(const float4*)&Vs[kv][tx * 4];
            o[0][0] += a0 * v4.x; o[0][1] += a0 * v4.y; o[0][2] += a0 * v4.z; o[0][3] += a0 * v4.w;
            o[1][0] += a1 * v4.x; o[1][1] += a1 * v4.y; o[1][2] += a1 * v4.z; o[1][3] += a1 * v4.w;
            o[2][0] += a2 * v4.x; o[2][1] += a2 * v4.y; o[2][2] += a2 * v4.z; o[2][3] += a2 * v4.w;
            o[3][0] += a3 * v4.x; o[3][1] += a3 * v4.y; o[3][2] += a3 * v4.z; o[3][3] += a3 * v4.w;
        }
    }

    // epilogue: normalize and store
#pragma unroll
    for (int i = 0; i < 4; i++) {
        const float inv = 1.f / l_i[i];
        float4 r;
        r.x = o[i][0] * inv; r.y = o[i][1] * inv; r.z = o[i][2] * inv; r.w = o[i][3] * inv;
        *(float4*)&out[((size_t)b * TT + qt * 64 + ty * 4 + i) * HH + tx * 4] = r;
    }
}

// ---------------------------------------------------------------------------
// Launch
// ---------------------------------------------------------------------------
extern "C" void kernel_launch(void* const* d_in, const int* in_sizes, int n_in,
                              void* d_out, int out_size)
{
    const float* x  = (const float*)d_in[0];
    const float* Wq = (const float*)d_in[1];
    const float* Wk = (const float*)d_in[2];
    const float* Wv = (const float*)d_in[3];
    float* out = (float*)d_out;

    (void)in_sizes; (void)n_in; (void)out_size;

    // QKV projection (tf32 tensor cores)
    {
        dim3 grid(BB * TT / 256, 3);
        proj_kernel<<<grid, 256>>>(x, Wq, Wk, Wv);
    }

    // Fused attention
    {
        const int smem_bytes = (3 * 64 * QT_STRIDE + 64 * 64) * (int)sizeof(float);
        cudaFuncSetAttribute(attn_kernel, cudaFuncAttributeMaxDynamicSharedMemorySize, smem_bytes);
        dim3 grid(TT / 64, BB);
        attn_kernel<<<grid, 256, smem_bytes>>>(out);
    }
}

// round 14
// speedup vs baseline: 2.5904x; 1.6149x over previous
#include <cuda_runtime.h>
#include <math.h>
#include <stdint.h>

// Problem constants
#define BB 64
#define TT 512
#define CC 384
#define HH 64

// Scratch for Q, K, V projections (8 MB each) — device globals, no allocation.
__device__ float g_q[BB * TT * HH];
__device__ float g_k[BB * TT * HH];
__device__ float g_v[BB * TT * HH];

// ---------------------------------------------------------------------------
// tf32 helpers
// ---------------------------------------------------------------------------
__device__ __forceinline__ uint32_t f2tf32(float f) {
    uint32_t u;
    asm("cvt.rna.tf32.f32 %0, %1;" : "=r"(u) : "f"(f));
    return u;
}

__device__ __forceinline__ void mma_tf32(float c[4], const uint32_t a[4],
                                         uint32_t b0, uint32_t b1) {
    asm volatile(
        "mma.sync.aligned.m16n8k8.row.col.f32.tf32.tf32.f32 "
        "{%0,%1,%2,%3}, {%4,%5,%6,%7}, {%8,%9}, {%0,%1,%2,%3};\n"
        : "+f"(c[0]), "+f"(c[1]), "+f"(c[2]), "+f"(c[3])
        : "r"(a[0]), "r"(a[1]), "r"(a[2]), "r"(a[3]), "r"(b0), "r"(b1));
}

// ---------------------------------------------------------------------------
// Projection kernel (tensor cores, tf32): out[m, h] = sum_c x[m, c] * W[c, h]
// (unchanged from R13 — proven at ~50us)
// ---------------------------------------------------------------------------
#define XS_ST 36   // A-frag bank = (g*36 + t) % 32 = g*4 + t -> 32 distinct
#define WS_ST 72   // holds 64-wide tile; B-frag bank = (t*8 + g + j*8) % 32 -> 32 distinct

__global__ __launch_bounds__(256) void proj_kernel(
    const float* __restrict__ x,
    const float* __restrict__ Wq,
    const float* __restrict__ Wk,
    const float* __restrict__ Wv)
{
    __shared__ __align__(16) uint32_t xs[256][XS_ST];  // x tile (tf32 bits), [m][k]
    __shared__ __align__(16) uint32_t ws[32][WS_ST];   // W tile (tf32 bits), [k][n]

    const int mt    = blockIdx.x;     // 0..127
    const int which = blockIdx.y;     // 0:Q 1:K 2:V
    const float* W  = (which == 0) ? Wq : (which == 1) ? Wk : Wv;
    float* outp     = (which == 0) ? g_q : (which == 1) ? g_k : g_v;

    const int tid  = threadIdx.x;
    const int warp = tid >> 5;
    const int lane = tid & 31;
    const int g    = lane >> 2;
    const int t    = lane & 3;
    const int m0   = mt * 256;
    const int mw   = warp * 32;

    float cf[16][4];
#pragma unroll
    for (int i = 0; i < 16; i++)
#pragma unroll
        for (int j = 0; j < 4; j++) cf[i][j] = 0.f;

    const int xc4 = (tid & 7) * 4;
    const int xr0 = tid >> 3;
    const int wc4 = (tid & 15) * 4;
    const int wr0 = tid >> 4;

    for (int k0 = 0; k0 < CC; k0 += 32) {
#pragma unroll
        for (int rr = xr0; rr < 256; rr += 32) {
            const float4 v = *(const float4*)&x[(size_t)(m0 + rr) * CC + k0 + xc4];
            uint4 u;
            u.x = f2tf32(v.x); u.y = f2tf32(v.y);
            u.z = f2tf32(v.z); u.w = f2tf32(v.w);
            *(uint4*)&xs[rr][xc4] = u;
        }
#pragma unroll
        for (int rr = wr0; rr < 32; rr += 16) {
            const float4 v = *(const float4*)&W[(k0 + rr) * HH + wc4];
            uint4 u;
            u.x = f2tf32(v.x); u.y = f2tf32(v.y);
            u.z = f2tf32(v.z); u.w = f2tf32(v.w);
            *(uint4*)&ws[rr][wc4] = u;
        }
        __syncthreads();

#pragma unroll
        for (int ks = 0; ks < 32; ks += 8) {
            uint32_t a0[4], a1[4];
            a0[0] = xs[mw + g     ][ks + t    ];
            a0[1] = xs[mw + g +  8][ks + t    ];
            a0[2] = xs[mw + g     ][ks + t + 4];
            a0[3] = xs[mw + g +  8][ks + t + 4];
            a1[0] = xs[mw + g + 16][ks + t    ];
            a1[1] = xs[mw + g + 24][ks + t    ];
            a1[2] = xs[mw + g + 16][ks + t + 4];
            a1[3] = xs[mw + g + 24][ks + t + 4];
#pragma unroll
            for (int j = 0; j < 8; j++) {
                const uint32_t b0 = ws[ks + t    ][j * 8 + g];
                const uint32_t b1 = ws[ks + t + 4][j * 8 + g];
                mma_tf32(cf[j],     a0, b0, b1);
                mma_tf32(cf[8 + j], a1, b0, b1);
            }
        }
        __syncthreads();
    }

#pragma unroll
    for (int mi = 0; mi < 2; mi++) {
#pragma unroll
        for (int j = 0; j < 8; j++) {
            const int row = m0 + mw + mi * 16 + g;
            const int col = j * 8 + 2 * t;
            float2 lo, hi;
            lo.x = cf[mi * 8 + j][0]; lo.y = cf[mi * 8 + j][1];
            hi.x = cf[mi * 8 + j][2]; hi.y = cf[mi * 8 + j][3];
            *(float2*)&outp[(size_t)row * HH + col]       = lo;
            *(float2*)&outp[(size_t)(row + 8) * HH + col] = hi;
        }
    }
}

// ---------------------------------------------------------------------------
// Tensor-core flash attention (tf32 m16n8k8).
// Grid: (T/64 q-tiles, B). Block 128 threads = 4 warps; warp w owns q rows
// [w*16, w*16+16) of the 64-row q tile. Q lives in A-fragments (registers,
// scale folded). Per kv tile: S via 64 mmas, softmax on C-fragments (rows g,
// g+8 per thread; row reduction = 2 shfl over t-lanes), P -> warp-private
// smem (tf32), reload as A-fragments, PV via 64 mmas.
// Smem banks: K/V stride 68 -> frag loads conflict-free; P stride 72 ->
// STS.64 conflict-free, LDS 2-way.
// ---------------------------------------------------------------------------
#define KV_ST 68
#define P_ST  72

__global__ __launch_bounds__(128) void attn_kernel(float* __restrict__ out)
{
    extern __shared__ __align__(16) uint32_t smu[];
    uint32_t (*Ks)[KV_ST] = (uint32_t(*)[KV_ST])smu;              // [64][68] K natural (tf32)
    uint32_t (*Vs)[KV_ST] = (uint32_t(*)[KV_ST])(smu + 64 * KV_ST); // [64][68] V natural (tf32)

    const int qt  = (int)gridDim.x - 1 - (int)blockIdx.x;  // heavy tiles first
    const int b   = blockIdx.y;
    const int tid = threadIdx.x;
    const int w   = tid >> 5;
    const int lane = tid & 31;
    const int g   = lane >> 2;   // 0..7
    const int t   = lane & 3;    // 0..3

    uint32_t* Pw = smu + 2 * 64 * KV_ST + w * 16 * P_ST;   // warp-private [16][72]

    // Q A-fragments, one per k-step (headdim/8), scale folded. Loaded once.
    uint32_t aq[8][4];
    {
        const float* qb = g_q + ((size_t)b * TT + qt * 64 + w * 16) * HH;
#pragma unroll
        for (int k = 0; k < 8; k++) {
            aq[k][0] = f2tf32(qb[(g    ) * HH + k * 8 + t    ] * 0.125f);
            aq[k][1] = f2tf32(qb[(g + 8) * HH + k * 8 + t    ] * 0.125f);
            aq[k][2] = f2tf32(qb[(g    ) * HH + k * 8 + t + 4] * 0.125f);
            aq[k][3] = f2tf32(qb[(g + 8) * HH + k * 8 + t + 4] * 0.125f);
        }
    }

    float m0 = -1e30f, m1 = -1e30f, l0 = 0.f, l1 = 0.f;
    float of[8][4];
#pragma unroll
    for (int j = 0; j < 8; j++)
#pragma unroll
        for (int i = 0; i < 4; i++) of[j][i] = 0.f;

    for (int kt = 0; kt <= qt; kt++) {
        __syncthreads();  // prior tile's K/V reads complete before overwrite

        // Cooperative load of K and V tiles (natural [key][h], tf32 bits)
        {
            const float* kb = g_k + ((size_t)b * TT + kt * 64) * HH;
            const float* vb = g_v + ((size_t)b * TT + kt * 64) * HH;
#pragma unroll
            for (int i = tid; i < 64 * 16; i += 128) {
                const int row = i >> 4;
                const int c4  = (i & 15) * 4;
                float4 kv = *(const float4*)&kb[row * HH + c4];
                uint4 u;
                u.x = f2tf32(kv.x); u.y = f2tf32(kv.y);
                u.z = f2tf32(kv.z); u.w = f2tf32(kv.w);
                *(uint4*)&Ks[row][c4] = u;
                kv = *(const float4*)&vb[row * HH + c4];
                u.x = f2tf32(kv.x); u.y = f2tf32(kv.y);
                u.z = f2tf32(kv.z); u.w = f2tf32(kv.w);
                *(uint4*)&Vs[row][c4] = u;
            }
        }
        __syncthreads();

        // ---- S = Q K^T : 8 n-tiles (keys) x 8 k-steps (headdim) ----
        float sc[8][4];
#pragma unroll
        for (int j = 0; j < 8; j++)
#pragma unroll
            for (int i = 0; i < 4; i++) sc[j][i] = 0.f;

#pragma unroll
        for (int k = 0; k < 8; k++) {
#pragma unroll
            for (int j = 0; j < 8; j++) {
                const uint32_t b0 = Ks[j * 8 + g][k * 8 + t    ];
                const uint32_t b1 = Ks[j * 8 + g][k * 8 + t + 4];
                mma_tf32(sc[j], aq[k], b0, b1);
            }
        }

        // ---- causal mask (diagonal tile only) ----
        if (kt == qt) {
            const int r0 = w * 16 + g;
            const int r1 = r0 + 8;
#pragma unroll
            for (int j = 0; j < 8; j++) {
                const int c0 = j * 8 + 2 * t;
                if (c0     > r0) sc[j][0] = -1e30f;
                if (c0 + 1 > r0) sc[j][1] = -1e30f;
                if (c0     > r1) sc[j][2] = -1e30f;
                if (c0 + 1 > r1) sc[j][3] = -1e30f;
            }
        }

        // ---- online softmax on C-fragments ----
        float mx0 = -1e30f, mx1 = -1e30f;
#pragma unroll
        for (int j = 0; j < 8; j++) {
            mx0 = fmaxf(mx0, fmaxf(sc[j][0], sc[j][1]));
            mx1 = fmaxf(mx1, fmaxf(sc[j][2], sc[j][3]));
        }
        mx0 = fmaxf(mx0, __shfl_xor_sync(0xffffffffu, mx0, 1));
        mx0 = fmaxf(mx0, __shfl_xor_sync(0xffffffffu, mx0, 2));
        mx1 = fmaxf(mx1, __shfl_xor_sync(0xffffffffu, mx1, 1));
        mx1 = fmaxf(mx1, __shfl_xor_sync(0xffffffffu, mx1, 2));

        const float mn0 = fmaxf(m0, mx0);
        const float mn1 = fmaxf(m1, mx1);
        const float al0 = __expf(m0 - mn0);
        const float al1 = __expf(m1 - mn1);
        m0 = mn0; m1 = mn1;

        float rs0 = 0.f, rs1 = 0.f;
#pragma unroll
        for (int j = 0; j < 8; j++) {
            const float p00 = __expf(sc[j][0] - m0);
            const float p01 = __expf(sc[j][1] - m0);
            const float p10 = __expf(sc[j][2] - m1);
            const float p11 = __expf(sc[j][3] - m1);
            rs0 += p00 + p01;
            rs1 += p10 + p11;
            uint2 u;
            u.x = f2tf32(p00); u.y = f2tf32(p01);
            *(uint2*)&Pw[(g    ) * P_ST + j * 8 + 2 * t] = u;
            u.x = f2tf32(p10); u.y = f2tf32(p11);
            *(uint2*)&Pw[(g + 8) * P_ST + j * 8 + 2 * t] = u;
            of[j][0] *= al0; of[j][1] *= al0;
            of[j][2] *= al1; of[j][3] *= al1;
        }
        rs0 += __shfl_xor_sync(0xffffffffu, rs0, 1);
        rs0 += __shfl_xor_sync(0xffffffffu, rs0, 2);
        rs1 += __shfl_xor_sync(0xffffffffu, rs1, 1);
        rs1 += __shfl_xor_sync(0xffffffffu, rs1, 2);
        l0 = l0 * al0 + rs0;
        l1 = l1 * al1 + rs1;

        __syncwarp();  // Pw is warp-private; make P visible to all lanes

        // ---- O += P @ V : 8 k-steps (keys) x 8 n-tiles (headdim) ----
#pragma unroll
        for (int k = 0; k < 8; k++) {
            uint32_t pa[4];
            pa[0] = Pw[(g    ) * P_ST + k * 8 + t    ];
            pa[1] = Pw[(g + 8) * P_ST + k * 8 + t    ];
            pa[2] = Pw[(g    ) * P_ST + k * 8 + t + 4];
            pa[3] = Pw[(g + 8) * P_ST + k * 8 + t + 4];
#pragma unroll
            for (int j = 0; j < 8; j++) {
                const uint32_t b0 = Vs[k * 8 + t    ][j * 8 + g];
                const uint32_t b1 = Vs[k * 8 + t + 4][j * 8 + g];
                mma_tf32(of[j], pa, b0, b1);
            }
        }
    }

    // ---- epilogue: normalize and store ----
    const float inv0 = 1.f / l0;
    const float inv1 = 1.f / l1;
    float* ob = out + ((size_t)b * TT + qt * 64 + w * 16) * HH;
#pragma unroll
    for (int j = 0; j < 8; j++) {
        float2 r;
        r.x = of[j][0] * inv0; r.y = of[j][1] * inv0;
        *(float2*)&ob[(g    ) * HH + j * 8 + 2 * t] = r;
        r.x = of[j][2] * inv1; r.y = of[j][3] * inv1;
        *(float2*)&ob[(g + 8) * HH + j * 8 + 2 * t] = r;
    }
}

// ---------------------------------------------------------------------------
// Launch
// ---------------------------------------------------------------------------
extern "C" void kernel_launch(void* const* d_in, const int* in_sizes, int n_in,
                              void* d_out, int out_size)
{
    const float* x  = (const float*)d_in[0];
    const float* Wq = (const float*)d_in[1];
    const float* Wk = (const float*)d_in[2];
    const float* Wv = (const float*)d_in[3];
    float* out = (float*)d_out;

    (void)in_sizes; (void)n_in; (void)out_size;

    // QKV projection (tf32 tensor cores)
    {
        dim3 grid(BB * TT / 256, 3);
        proj_kernel<<<grid, 256>>>(x, Wq, Wk, Wv);
    }

    // Fused attention (tf32 tensor cores)
    {
        const int smem_bytes = (2 * 64 * KV_ST + 4 * 16 * P_ST) * (int)sizeof(uint32_t);
        cudaFuncSetAttribute(attn_kernel, cudaFuncAttributeMaxDynamicSharedMemorySize, smem_bytes);
        dim3 grid(TT / 64, BB);
        attn_kernel<<<grid, 128, smem_bytes>>>(out);
    }
}